// round 8
// baseline (speedup 1.0000x reference)
#include <cuda_runtime.h>
#include <cuda_bf16.h>

// CubePad: x [6N, C, 256, 256] -> out [6N, C, 258, 258]
// Face order: 0 front, 1 right, 2 back, 3 left, 4 top, 5 down.
//
// v8: output-flat mapping. One thread per output float4 (face-channel output
// = 16641 float4s exactly, 16B aligned), so the entire 204MB write stream is
// aligned contiguous STG.128 with no cross-warp sector sharing and no STG.64
// tails. Interior sources are 4 contiguous scalar loads; float4s touching a
// row boundary / border column / plate row take a per-element gather.

#define Hh 256
#define Ww 256
#define Cc 64
#define HP 258
#define WP 258
#define FACE_IN   (Hh * Ww)
#define FACE_OUT  (HP * WP)      // 66564 floats
#define Q_PER_NFC (FACE_OUT / 4) // 16641 float4s
#define CF        (Cc * FACE_IN) // face stride in floats

// generic padded-value gather for boundary elements
__device__ __forceinline__ float cube_value(
    const float* __restrict__ base, int f, int r, int w)
{
    if (r >= 1 && r <= Hh) {
        int h = r - 1;
        if (w >= 1 && w <= Ww)
            return base[f * CF + h * Ww + (w - 1)];
        int off, str;
        if (w == 0) {            // left border
            switch (f) {
                case 0: off = 3*CF + (Ww-1); str = Ww; break;
                case 1: off = 0*CF + (Ww-1); str = Ww; break;
                case 2: off = 1*CF + (Ww-1); str = Ww; break;
                case 3: off = 2*CF + (Ww-1); str = Ww; break;
                case 4: off = 3*CF;          str = 1;  break;
                default:off = 3*CF + (Hh-1)*Ww + (Ww-1); str = -1; break;
            }
        } else {                 // right border (w == 257)
            switch (f) {
                case 0: off = 1*CF;          str = Ww; break;
                case 1: off = 2*CF;          str = Ww; break;
                case 2: off = 3*CF;          str = Ww; break;
                case 3: off = 0*CF;          str = Ww; break;
                case 4: off = 1*CF + (Ww-1); str = -1; break;
                default:off = 1*CF + (Hh-1)*Ww; str = 1; break;
            }
        }
        return base[off + h * str];
    }
    // plate rows; corners are clamp of the plate formula (p=1)
    int wc = w - 1;
    wc = wc < 0 ? 0 : (wc > Ww - 1 ? Ww - 1 : wc);
    int off, str;
    if (r == 0) {                // top plate
        switch (f) {
            case 0:  off = 4*CF + (Hh-1)*Ww;          str = 1;   break;
            case 1:  off = 4*CF + (Hh-1)*Ww + (Ww-1); str = -Ww; break;
            case 2:  off = 4*CF + (Ww-1);             str = -1;  break;
            case 3:  off = 4*CF;                      str = Ww;  break;
            case 4:  off = 2*CF + (Ww-1);             str = -1;  break;
            default: off = 0*CF + (Hh-1)*Ww;          str = 1;   break;
        }
    } else {                     // down plate (r == 257)
        switch (f) {
            case 0:  off = 5*CF;                      str = 1;   break;
            case 1:  off = 5*CF + (Ww-1);             str = Ww;  break;
            case 2:  off = 5*CF + (Hh-1)*Ww + (Ww-1); str = -1;  break;
            case 3:  off = 5*CF + (Hh-1)*Ww;          str = -Ww; break;
            case 4:  off = 0*CF;                      str = 1;   break;
            default: off = 2*CF + (Hh-1)*Ww + (Ww-1); str = -1;  break;
        }
    }
    return base[off + wc * str];
}

__global__ void __launch_bounds__(256, 6) cubepad_flat(
    const float* __restrict__ in, float* __restrict__ out, int total_q)
{
    int q = blockIdx.x * blockDim.x + threadIdx.x;
    if (q >= total_q) return;

    int nfc = q / Q_PER_NFC;          // face-channel (float4-aligned)
    int p   = (q - nfc * Q_PER_NFC) * 4;   // local float offset 0..66560
    int r   = p / WP;
    int w0  = p - r * WP;

    int f = (nfc >> 6) % 6;
    const float* base = in + (nfc - f * Cc) * FACE_IN;

    float4 v;
    if (r >= 1 && r <= Hh && w0 >= 1 && w0 <= 253) {
        // fast path: all 4 elements interior, same row
        const float* s = base + f * CF + (r - 1) * Ww + (w0 - 1);
        v.x = s[0]; v.y = s[1]; v.z = s[2]; v.w = s[3];
    } else {
        // boundary: per-element gather (may cross row boundary)
        v.x = cube_value(base, f, r, w0);
        int p1 = p + 1; v.y = cube_value(base, f, p1 / WP, p1 % WP);
        int p2 = p + 2; v.z = cube_value(base, f, p2 / WP, p2 % WP);
        int p3 = p + 3; v.w = cube_value(base, f, p3 / WP, p3 % WP);
    }
    reinterpret_cast<float4*>(out)[q] = v;
}

extern "C" void kernel_launch(void* const* d_in, const int* in_sizes, int n_in,
                              void* d_out, int out_size)
{
    const float* x = (const float*)d_in[0];
    float* out = (float*)d_out;

    int total_in  = in_sizes[0];            // 6N * C * H * W
    int nfc_total = total_in / FACE_IN;     // 6N * C
    int total_q   = nfc_total * Q_PER_NFC;  // output float4 count

    int blocks = (total_q + 255) / 256;
    cubepad_flat<<<blocks, 256>>>(x, out, total_q);
}